// round 14
// baseline (speedup 1.0000x reference)
#include <cuda_runtime.h>
#include <cuda_bf16.h>
#include <cstdint>

// ---------------------------------------------------------------------------
// GatedShortBlock via split-bf16 HMMA (mma.sync):
//   bcx = x @ w1^T   (16384 x 6144, K=2048)
//   u   = Cg * causal_conv4(Bg * Xg)
//   out = u @ w2^T   (16384 x 2048, K=2048)
// C = Ah*Bh^T + Ah*Bl^T + Al*Bh^T  (bf16 operands, fp32 accum, err ~2^-17)
// R14: R11 (best: 3220us) + rolling stage/K pointers: the (kt%3)*STAGE_B and
//      kt*64 index chains replaced by add/wrap registers. R13's mid-slab
//      barrier reverted (regressed; 2-CTA overlap already hides convergence).
// ---------------------------------------------------------------------------

#define D_MODEL 2048
#define SEQ     4096
#define MTOK    16384
#define N1      6144
#define KEL     2048
#define KT      64            // 2048 / 32 k-slabs
#define KSZ     4

// ---------------- scratch ----------------------------------------------------
__device__ __align__(16) __nv_bfloat16 g_xh [(size_t)MTOK * KEL];
__device__ __align__(16) __nv_bfloat16 g_xl [(size_t)MTOK * KEL];
__device__ __align__(16) __nv_bfloat16 g_w1h[(size_t)N1 * KEL];
__device__ __align__(16) __nv_bfloat16 g_w1l[(size_t)N1 * KEL];
__device__ __align__(16) __nv_bfloat16 g_w2h[(size_t)D_MODEL * KEL];
__device__ __align__(16) __nv_bfloat16 g_w2l[(size_t)D_MODEL * KEL];
__device__ __align__(16) __nv_bfloat16 g_uh [(size_t)MTOK * KEL];
__device__ __align__(16) __nv_bfloat16 g_ul [(size_t)MTOK * KEL];
__device__ float g_bcx[(size_t)MTOK * N1];

// ---------------- asm helpers ------------------------------------------------
__device__ __forceinline__ uint32_t smem_u32(const void* p) {
    uint32_t a;
    asm("{ .reg .u64 t; cvta.to.shared.u64 t, %1; cvt.u32.u64 %0, t; }" : "=r"(a) : "l"(p));
    return a;
}
__device__ __forceinline__ void cp16(uint32_t dst, const void* src) {
    asm volatile("cp.async.cg.shared.global [%0], [%1], 16;" :: "r"(dst), "l"(src));
}
#define CP_COMMIT() asm volatile("cp.async.commit_group;" ::: "memory")
#define CP_WAIT1()  asm volatile("cp.async.wait_group 1;" ::: "memory")

#define LDSM_X4(r0, r1, r2, r3, addr) \
    asm volatile("ldmatrix.sync.aligned.m8n8.x4.shared.b16 {%0,%1,%2,%3}, [%4];" \
        : "=r"(r0), "=r"(r1), "=r"(r2), "=r"(r3) : "r"(addr))

#define MMA16816(c, a0, a1, a2, a3, b0, b1) \
    asm volatile("mma.sync.aligned.m16n8k16.row.col.f32.bf16.bf16.f32 " \
        "{%0,%1,%2,%3}, {%4,%5,%6,%7}, {%8,%9}, {%0,%1,%2,%3};" \
        : "+f"((c)[0]), "+f"((c)[1]), "+f"((c)[2]), "+f"((c)[3]) \
        : "r"(a0), "r"(a1), "r"(a2), "r"(a3), "r"(b0), "r"(b1))

// ---------------------------------------------------------------------------
// GEMM kernel. CTA tile 128x128, 256 threads, warp grid 2(m) x 4(n),
// warp tile 64x32. Smem per stage (32KB): [Ah 8K | Al 8K | Bh 8K | Bl 8K],
// 64B rows, 16B chunks XOR-swizzled by ((row>>1)&3). 3 stages -> 2 CTAs/SM.
// ---------------------------------------------------------------------------
#define STAGE_B   32768
#define GEMM_SMEM (3 * STAGE_B)   // 98304

__global__ __launch_bounds__(256, 2) void gemm_split(
    const __nv_bfloat16* __restrict__ Ah, const __nv_bfloat16* __restrict__ Al,
    const __nv_bfloat16* __restrict__ Bh, const __nv_bfloat16* __restrict__ Bl,
    float* __restrict__ C, int Ntot)
{
    extern __shared__ __align__(1024) char smem[];
    const uint32_t sb = smem_u32(smem);
    const int tid  = threadIdx.x;
    const int lane = tid & 31;
    const int wid  = tid >> 5;
    const int wm   = wid >> 2;        // 0..1  (m)
    const int wn   = wid & 3;         // 0..3  (n)

    const size_t m0 = (size_t)blockIdx.y * 128;
    const size_t n0 = (size_t)blockIdx.x * 128;

    // Per-thread cp.async source bases (row/chunk fixed per thread).
    const int ldrow = tid >> 2;          // handled below per rep
    (void)ldrow;
    const char* pAh = (const char*)(Ah + m0 * (size_t)KEL);
    const char* pAl = (const char*)(Al + m0 * (size_t)KEL);
    const char* pBh = (const char*)(Bh + n0 * (size_t)KEL);
    const char* pBl = (const char*)(Bl + n0 * (size_t)KEL);

    // load_stage with explicit stage base + K byte offset (no modulo).
    auto load_stage = [&](uint32_t st, uint32_t kb) {
        #pragma unroll
        for (int rep = 0; rep < 2; rep++) {   // 128 rows x 4 chunks = 512 slots
            const int idx = rep * 256 + tid;
            const int row = idx >> 2, c = idx & 3;
            const uint32_t sw = ((((uint32_t)c) ^ ((row >> 1) & 3)) << 4);
            const uint32_t dA = st + row * 64 + sw;
            const uint32_t dB = st + 16384 + row * 64 + sw;
            const size_t so = (size_t)row * (KEL * 2) + kb + c * 16;
            cp16(dA,        pAh + so);
            cp16(dA + 8192, pAl + so);
            cp16(dB,        pBh + so);
            cp16(dB + 8192, pBl + so);
        }
    };

    // Prologue: 2 stages in flight (3rd buffer free for the first prefetch).
    load_stage(sb,            0);  CP_COMMIT();
    load_stage(sb + STAGE_B, 64);  CP_COMMIT();

    float acc[4][4][4];
    #pragma unroll
    for (int i = 0; i < 4; i++)
        #pragma unroll
        for (int j = 0; j < 4; j++)
            #pragma unroll
            for (int q = 0; q < 4; q++) acc[i][j][q] = 0.0f;

    const int lrow8  = lane & 7;
    const int lhalfA = (lane >> 3) & 1;
    const int lkA    = lane >> 4;
    const int lhalfB = lane >> 4;
    const int lkB    = (lane >> 3) & 1;

    // kt-invariant LDSM offsets (relative to stage base). kc=1 addr = kc=0 ^ 32.
    uint32_t oA[4], oB[2];
    #pragma unroll
    for (int i = 0; i < 4; i++) {
        const int row = wm * 64 + i * 16 + lrow8 + lhalfA * 8;
        oA[i] = row * 64 + ((((uint32_t)lkA) ^ ((row >> 1) & 3)) << 4);
    }
    #pragma unroll
    for (int jp = 0; jp < 2; jp++) {
        const int nrow = wn * 32 + jp * 16 + lrow8 + lhalfB * 8;
        oB[jp] = 16384 + nrow * 64 + ((((uint32_t)lkB) ^ ((nrow >> 1) & 3)) << 4);
    }

    // Rolling pointers: consume stage, prefetch stage, prefetch K offset.
    uint32_t st_cons = sb;                 // stage being consumed this iter
    uint32_t st_pref = sb + 2 * STAGE_B;   // free buffer for prefetch
    uint32_t kb_pref = 2 * 64;             // K byte-offset of prefetch slab
    const uint32_t st_end = sb + 3 * STAGE_B;
    const uint32_t kb_end = KT * 64;

    for (int kt = 0; kt < KT; kt++) {
        CP_WAIT1();            // stage kt complete (kt+1 may still be in flight)
        __syncthreads();

        if (kb_pref < kb_end) load_stage(st_pref, kb_pref);
        CP_COMMIT();
        kb_pref += 64;
        st_pref += STAGE_B; if (st_pref == st_end) st_pref = sb;

        const uint32_t st = st_cons;
        st_cons += STAGE_B; if (st_cons == st_end) st_cons = sb;

        #pragma unroll
        for (int ks = 0; ks < 2; ks++) {
            const uint32_t kx = (ks == 0) ? 0u : 32u;

            uint32_t bh[4][2], bl[4][2];
            #pragma unroll
            for (int jp = 0; jp < 2; jp++) {
                const uint32_t bd = st + (oB[jp] ^ kx);
                LDSM_X4(bh[jp*2][0], bh[jp*2][1], bh[jp*2+1][0], bh[jp*2+1][1], bd);
                LDSM_X4(bl[jp*2][0], bl[jp*2][1], bl[jp*2+1][0], bl[jp*2+1][1], bd + 8192);
            }
            uint32_t ahf[4][4], alf[4][4];
            {
                const uint32_t ad = st + (oA[0] ^ kx);
                LDSM_X4(ahf[0][0], ahf[0][1], ahf[0][2], ahf[0][3], ad);
                LDSM_X4(alf[0][0], alf[0][1], alf[0][2], alf[0][3], ad + 8192);
            }
            #pragma unroll
            for (int i = 0; i < 4; i++) {
                if (i < 3) {
                    const uint32_t ad = st + (oA[i + 1] ^ kx);
                    LDSM_X4(ahf[i+1][0], ahf[i+1][1], ahf[i+1][2], ahf[i+1][3], ad);
                    LDSM_X4(alf[i+1][0], alf[i+1][1], alf[i+1][2], alf[i+1][3], ad + 8192);
                }
                #pragma unroll
                for (int jp = 0; jp < 2; jp++) {
                    float* c0 = acc[i][jp * 2];
                    float* c1 = acc[i][jp * 2 + 1];
                    MMA16816(c0, ahf[i][0], ahf[i][1], ahf[i][2], ahf[i][3], bh[jp*2][0], bh[jp*2][1]);
                    MMA16816(c0, ahf[i][0], ahf[i][1], ahf[i][2], ahf[i][3], bl[jp*2][0], bl[jp*2][1]);
                    MMA16816(c0, alf[i][0], alf[i][1], alf[i][2], alf[i][3], bh[jp*2][0], bh[jp*2][1]);
                    MMA16816(c1, ahf[i][0], ahf[i][1], ahf[i][2], ahf[i][3], bh[jp*2+1][0], bh[jp*2+1][1]);
                    MMA16816(c1, ahf[i][0], ahf[i][1], ahf[i][2], ahf[i][3], bl[jp*2+1][0], bl[jp*2+1][1]);
                    MMA16816(c1, alf[i][0], alf[i][1], alf[i][2], alf[i][3], bh[jp*2+1][0], bh[jp*2+1][1]);
                }
            }
        }
    }

    // ---- epilogue -----------------------------------------------------------
    #pragma unroll
    for (int i = 0; i < 4; i++) {
        const size_t r = m0 + wm * 64 + i * 16 + (lane >> 2);
        #pragma unroll
        for (int j = 0; j < 4; j++) {
            const size_t c = n0 + wn * 32 + j * 8 + (lane & 3) * 2;
            *reinterpret_cast<float2*>(C + r * (size_t)Ntot + c) =
                make_float2(acc[i][j][0], acc[i][j][1]);
            *reinterpret_cast<float2*>(C + (r + 8) * (size_t)Ntot + c) =
                make_float2(acc[i][j][2], acc[i][j][3]);
        }
    }
}

// NOTE: prefetch is issued BEFORE the ks loops here (as in R8/R11 topology the
// commit must follow the wait+bar; keeping it at slab top preserves the R11
// group structure: exactly one commit per iteration, wait_group 1 semantics).

// ---------------------------------------------------------------------------
// Merged fp32 -> (hi, lo) bf16 split for x, w1, w2 in ONE launch.
// ---------------------------------------------------------------------------
#define GX   ((size_t)MTOK * KEL / 8)
#define GW1  ((size_t)N1 * KEL / 8)
#define GW2  ((size_t)D_MODEL * KEL / 8)
#define GTOT (GX + GW1 + GW2)

__global__ __launch_bounds__(256) void split_all(
    const float* __restrict__ x,  const float* __restrict__ w1, const float* __restrict__ w2,
    __nv_bfloat16* __restrict__ xh,  __nv_bfloat16* __restrict__ xl,
    __nv_bfloat16* __restrict__ w1h, __nv_bfloat16* __restrict__ w1l,
    __nv_bfloat16* __restrict__ w2h, __nv_bfloat16* __restrict__ w2l)
{
    size_t g = (size_t)blockIdx.x * blockDim.x + threadIdx.x;
    if (g >= GTOT) return;
    const float* src;
    __nv_bfloat16 *hi, *lo;
    size_t off;
    if (g < GX)            { src = x;  hi = xh;  lo = xl;  off = g; }
    else if (g < GX + GW1) { src = w1; hi = w1h; lo = w1l; off = g - GX; }
    else                   { src = w2; hi = w2h; lo = w2l; off = g - GX - GW1; }

    const float* s = src + off * 8;
    float4 v0 = *reinterpret_cast<const float4*>(s);
    float4 v1 = *reinterpret_cast<const float4*>(s + 4);
    float v[8] = {v0.x, v0.y, v0.z, v0.w, v1.x, v1.y, v1.z, v1.w};
    union { __nv_bfloat16 h[8]; uint4 u; } H, L;
    #pragma unroll
    for (int i = 0; i < 8; i++) {
        __nv_bfloat16 h = __float2bfloat16(v[i]);
        H.h[i] = h;
        L.h[i] = __float2bfloat16(v[i] - __bfloat162float(h));
    }
    *reinterpret_cast<uint4*>(hi + off * 8) = H.u;
    *reinterpret_cast<uint4*>(lo + off * 8) = L.u;
}

// ---------------------------------------------------------------------------
// Fused gate + causal depthwise conv(K=4) + gate; outputs split bf16 u.
// Register-rolling: each thread owns 8 d-cols x 64 consecutive tokens,
// keeps last 3 gated vectors in a 4-slot register ring -> 3 reads/element.
// Strips never cross sequence boundaries (4096 % 64 == 0).
// ---------------------------------------------------------------------------
#define STRIP 64

__global__ __launch_bounds__(256) void conv_gate_roll(
    const float* __restrict__ bcx, const float* __restrict__ cw,
    __nv_bfloat16* __restrict__ uh, __nv_bfloat16* __restrict__ ul)
{
    const int t = blockIdx.x * blockDim.x + threadIdx.x;
    if (t >= (MTOK / STRIP) * 256) return;
    const int dg    = t & 255;          // d-group (8 cols)
    const int strip = t >> 8;
    const int d0 = dg * 8;
    const size_t m0 = (size_t)strip * STRIP;
    const int s0 = (int)(m0 % SEQ);     // within-sequence start

    float w[8][4];
    #pragma unroll
    for (int j = 0; j < 8; j++) {
        float4 wv = *reinterpret_cast<const float4*>(cw + (size_t)(d0 + j) * 4);
        w[j][0] = wv.x; w[j][1] = wv.y; w[j][2] = wv.z; w[j][3] = wv.w;
    }

    float g[4][8];
    #pragma unroll
    for (int q = 0; q < 3; q++) {
        #pragma unroll
        for (int j = 0; j < 8; j++) g[q][j] = 0.0f;
        if (s0 > 0) {   // preload gated[m0-3+q]
            const float* row = bcx + (m0 - 3 + q) * (size_t)N1;
            float4 b0 = *reinterpret_cast<const float4*>(row + d0);
            float4 b1 = *reinterpret_cast<const float4*>(row + d0 + 4);
            float4 x0 = *reinterpret_cast<const float4*>(row + 2 * D_MODEL + d0);
            float4 x1 = *reinterpret_cast<const float4*>(row + 2 * D_MODEL + d0 + 4);
            float bb[8] = {b0.x, b0.y, b0.z, b0.w, b1.x, b1.y, b1.z, b1.w};
            float xx[8] = {x0.x, x0.y, x0.z, x0.w, x1.x, x1.y, x1.z, x1.w};
            #pragma unroll
            for (int j = 0; j < 8; j++) g[q][j] = bb[j] * xx[j];
        }
    }

    #pragma unroll 4
    for (int tt = 0; tt < STRIP; tt++) {
        const size_t m = m0 + tt;
        const float* row = bcx + m * (size_t)N1;
        float4 b0 = *reinterpret_cast<const float4*>(row + d0);
        float4 b1 = *reinterpret_cast<const float4*>(row + d0 + 4);
        float4 x0 = *reinterpret_cast<const float4*>(row + 2 * D_MODEL + d0);
        float4 x1 = *reinterpret_cast<const float4*>(row + 2 * D_MODEL + d0 + 4);
        float bb[8] = {b0.x, b0.y, b0.z, b0.w, b1.x, b1.y, b1.z, b1.w};
        float xx[8] = {x0.x, x0.y, x0.z, x0.w, x1.x, x1.y, x1.z, x1.w};
        float* gc = g[(tt + 3) & 3];
        #pragma unroll
        for (int j = 0; j < 8; j++) gc[j] = bb[j] * xx[j];

        const float* g3 = g[tt & 3];        // token m-3
        const float* g2 = g[(tt + 1) & 3];  // token m-2
        const float* g1 = g[(tt + 2) & 3];  // token m-1

        float4 c0 = *reinterpret_cast<const float4*>(row + D_MODEL + d0);
        float4 c1 = *reinterpret_cast<const float4*>(row + D_MODEL + d0 + 4);
        float cc[8] = {c0.x, c0.y, c0.z, c0.w, c1.x, c1.y, c1.z, c1.w};

        union { __nv_bfloat16 h[8]; uint4 u; } H, L;
        #pragma unroll
        for (int j = 0; j < 8; j++) {
            float a = g3[j] * w[j][0];
            a = fmaf(g2[j], w[j][1], a);
            a = fmaf(g1[j], w[j][2], a);
            a = fmaf(gc[j], w[j][3], a);
            float u = cc[j] * a;
            __nv_bfloat16 h = __float2bfloat16(u);
            H.h[j] = h;
            L.h[j] = __float2bfloat16(u - __bfloat162float(h));
        }
        const size_t off = m * (size_t)D_MODEL + d0;
        *reinterpret_cast<uint4*>(uh + off) = H.u;
        *reinterpret_cast<uint4*>(ul + off) = L.u;
    }
}

// ---------------------------------------------------------------------------
extern "C" void kernel_launch(void* const* d_in, const int* in_sizes, int n_in,
                              void* d_out, int out_size)
{
    const float* x  = (const float*)d_in[0];
    const float* w1 = (const float*)d_in[1];
    const float* w2 = (const float*)d_in[2];
    const float* cw = (const float*)d_in[3];
    float* out = (float*)d_out;

    __nv_bfloat16 *xh, *xl, *w1h, *w1l, *w2h, *w2l, *uh, *ul;
    float* bcx;
    cudaGetSymbolAddress((void**)&xh,  g_xh);
    cudaGetSymbolAddress((void**)&xl,  g_xl);
    cudaGetSymbolAddress((void**)&w1h, g_w1h);
    cudaGetSymbolAddress((void**)&w1l, g_w1l);
    cudaGetSymbolAddress((void**)&w2h, g_w2h);
    cudaGetSymbolAddress((void**)&w2l, g_w2l);
    cudaGetSymbolAddress((void**)&uh,  g_uh);
    cudaGetSymbolAddress((void**)&ul,  g_ul);
    cudaGetSymbolAddress((void**)&bcx, g_bcx);

    cudaFuncSetAttribute(gemm_split,
                         cudaFuncAttributeMaxDynamicSharedMemorySize, GEMM_SMEM);

    // One merged split launch for x, w1, w2.
    split_all<<<(int)((GTOT + 255) / 256), 256>>>(
        x, w1, w2, xh, xl, w1h, w1l, w2h, w2l);

    // GEMM1: bcx = x @ w1^T
    {
        dim3 grid(N1 / 128, MTOK / 128);
        gemm_split<<<grid, 256, GEMM_SMEM>>>(xh, xl, w1h, w1l, bcx, N1);
    }

    // fused gate/conv/gate -> uh, ul (register-rolling strips)
    conv_gate_roll<<<((MTOK / STRIP) * 256) / 256, 256>>>(bcx, cw, uh, ul);

    // GEMM2: out = u @ w2^T
    {
        dim3 grid(D_MODEL / 128, MTOK / 128);
        gemm_split<<<grid, 256, GEMM_SMEM>>>(uh, ul, w2h, w2l, out, D_MODEL);
    }
}

// round 15
// speedup vs baseline: 1.0623x; 1.0623x over previous
#include <cuda_runtime.h>
#include <cuda_bf16.h>
#include <cstdint>

// ---------------------------------------------------------------------------
// GatedShortBlock via split-bf16 HMMA (mma.sync):
//   bcx = x @ w1^T   (16384 x 6144, K=2048)
//   u   = Cg * causal_conv4(Bg * Xg)
//   out = u @ w2^T   (16384 x 2048, K=2048)
// C = Ah*Bh^T + Ah*Bl^T + Al*Bh^T  (bf16 operands, fp32 accum, err ~2^-17)
// R15 = R11 restored verbatim (session best, 3219.9us):
//   - CTA tile 128x128, 256 thr, warp 64x32, 3-stage cp.async, 2 CTAs/SM
//   - B+A[0] LDSM first, A[i+1] interleaved under MMAs of A[i]   (R9 win)
//   - prefetch issued BETWEEN ks=0 and ks=1, hidden under MMAs    (R9 win)
//   - hoisted kt-invariant LDSM offsets, kc=1 via XOR 32          (R11 win)
//   - merged split kernel, STRIP-64 register-rolling conv         (R10/11 wins)
// R12 (counter fusion), R13 (mid-slab barrier), R14 (slab-top prefetch +
// rolling ptrs) all regressed or were neutral -> rejected.
// ---------------------------------------------------------------------------

#define D_MODEL 2048
#define SEQ     4096
#define MTOK    16384
#define N1      6144
#define KEL     2048
#define KT      64            // 2048 / 32 k-slabs
#define KSZ     4

// ---------------- scratch ----------------------------------------------------
__device__ __align__(16) __nv_bfloat16 g_xh [(size_t)MTOK * KEL];
__device__ __align__(16) __nv_bfloat16 g_xl [(size_t)MTOK * KEL];
__device__ __align__(16) __nv_bfloat16 g_w1h[(size_t)N1 * KEL];
__device__ __align__(16) __nv_bfloat16 g_w1l[(size_t)N1 * KEL];
__device__ __align__(16) __nv_bfloat16 g_w2h[(size_t)D_MODEL * KEL];
__device__ __align__(16) __nv_bfloat16 g_w2l[(size_t)D_MODEL * KEL];
__device__ __align__(16) __nv_bfloat16 g_uh [(size_t)MTOK * KEL];
__device__ __align__(16) __nv_bfloat16 g_ul [(size_t)MTOK * KEL];
__device__ float g_bcx[(size_t)MTOK * N1];

// ---------------- asm helpers ------------------------------------------------
__device__ __forceinline__ uint32_t smem_u32(const void* p) {
    uint32_t a;
    asm("{ .reg .u64 t; cvta.to.shared.u64 t, %1; cvt.u32.u64 %0, t; }" : "=r"(a) : "l"(p));
    return a;
}
__device__ __forceinline__ void cp16(uint32_t dst, const void* src) {
    asm volatile("cp.async.cg.shared.global [%0], [%1], 16;" :: "r"(dst), "l"(src));
}
#define CP_COMMIT() asm volatile("cp.async.commit_group;" ::: "memory")
#define CP_WAIT1()  asm volatile("cp.async.wait_group 1;" ::: "memory")

#define LDSM_X4(r0, r1, r2, r3, addr) \
    asm volatile("ldmatrix.sync.aligned.m8n8.x4.shared.b16 {%0,%1,%2,%3}, [%4];" \
        : "=r"(r0), "=r"(r1), "=r"(r2), "=r"(r3) : "r"(addr))

#define MMA16816(c, a0, a1, a2, a3, b0, b1) \
    asm volatile("mma.sync.aligned.m16n8k16.row.col.f32.bf16.bf16.f32 " \
        "{%0,%1,%2,%3}, {%4,%5,%6,%7}, {%8,%9}, {%0,%1,%2,%3};" \
        : "+f"((c)[0]), "+f"((c)[1]), "+f"((c)[2]), "+f"((c)[3]) \
        : "r"(a0), "r"(a1), "r"(a2), "r"(a3), "r"(b0), "r"(b1))

// ---------------------------------------------------------------------------
// GEMM kernel. CTA tile 128x128, 256 threads, warp grid 2(m) x 4(n),
// warp tile 64x32. Smem per stage (32KB): [Ah 8K | Al 8K | Bh 8K | Bl 8K],
// 64B rows, 16B chunks XOR-swizzled by ((row>>1)&3). 3 stages -> 2 CTAs/SM.
// ---------------------------------------------------------------------------
#define STAGE_B   32768
#define GEMM_SMEM (3 * STAGE_B)   // 98304

__global__ __launch_bounds__(256, 2) void gemm_split(
    const __nv_bfloat16* __restrict__ Ah, const __nv_bfloat16* __restrict__ Al,
    const __nv_bfloat16* __restrict__ Bh, const __nv_bfloat16* __restrict__ Bl,
    float* __restrict__ C, int Ntot)
{
    extern __shared__ __align__(1024) char smem[];
    const uint32_t sb = smem_u32(smem);
    const int tid  = threadIdx.x;
    const int lane = tid & 31;
    const int wid  = tid >> 5;
    const int wm   = wid >> 2;        // 0..1  (m)
    const int wn   = wid & 3;         // 0..3  (n)

    const size_t m0 = (size_t)blockIdx.y * 128;
    const size_t n0 = (size_t)blockIdx.x * 128;

    const char* pAh = (const char*)(Ah + m0 * (size_t)KEL);
    const char* pAl = (const char*)(Al + m0 * (size_t)KEL);
    const char* pBh = (const char*)(Bh + n0 * (size_t)KEL);
    const char* pBl = (const char*)(Bl + n0 * (size_t)KEL);

    auto load_stage = [&](int s, int kt) {
        const uint32_t st = sb + s * STAGE_B;
        const size_t kb = (size_t)kt * 64;   // byte offset along K
        #pragma unroll
        for (int rep = 0; rep < 2; rep++) {   // 128 rows x 4 chunks = 512 slots
            const int idx = rep * 256 + tid;
            const int row = idx >> 2, c = idx & 3;
            const uint32_t sw = ((((uint32_t)c) ^ ((row >> 1) & 3)) << 4);
            const uint32_t dA = st + row * 64 + sw;
            const uint32_t dB = st + 16384 + row * 64 + sw;
            const size_t so = (size_t)row * (KEL * 2) + kb + c * 16;
            cp16(dA,        pAh + so);
            cp16(dA + 8192, pAl + so);
            cp16(dB,        pBh + so);
            cp16(dB + 8192, pBl + so);
        }
    };

    // Prologue: 2 stages in flight (3rd buffer free for the first prefetch).
    load_stage(0, 0); CP_COMMIT();
    load_stage(1, 1); CP_COMMIT();

    float acc[4][4][4];
    #pragma unroll
    for (int i = 0; i < 4; i++)
        #pragma unroll
        for (int j = 0; j < 4; j++)
            #pragma unroll
            for (int q = 0; q < 4; q++) acc[i][j][q] = 0.0f;

    const int lrow8  = lane & 7;
    const int lhalfA = (lane >> 3) & 1;
    const int lkA    = lane >> 4;
    const int lhalfB = lane >> 4;
    const int lkB    = (lane >> 3) & 1;

    // kt-invariant LDSM offsets (relative to stage base). kc=1 addr = kc=0 ^ 32.
    uint32_t oA[4], oB[2];
    #pragma unroll
    for (int i = 0; i < 4; i++) {
        const int row = wm * 64 + i * 16 + lrow8 + lhalfA * 8;
        oA[i] = row * 64 + ((((uint32_t)lkA) ^ ((row >> 1) & 3)) << 4);
    }
    #pragma unroll
    for (int jp = 0; jp < 2; jp++) {
        const int nrow = wn * 32 + jp * 16 + lrow8 + lhalfB * 8;
        oB[jp] = 16384 + nrow * 64 + ((((uint32_t)lkB) ^ ((nrow >> 1) & 3)) << 4);
    }

    for (int kt = 0; kt < KT; kt++) {
        CP_WAIT1();            // stage kt complete (kt+1 may still be in flight)
        __syncthreads();

        const uint32_t st = sb + (kt % 3) * STAGE_B;
        #pragma unroll
        for (int ks = 0; ks < 2; ks++) {
            const uint32_t kx = (ks == 0) ? 0u : 32u;

            // ---- B fragments for both jp first (MMAs for i=0 need them) ----
            uint32_t bh[4][2], bl[4][2];
            #pragma unroll
            for (int jp = 0; jp < 2; jp++) {
                const uint32_t bd = st + (oB[jp] ^ kx);
                LDSM_X4(bh[jp*2][0], bh[jp*2][1], bh[jp*2+1][0], bh[jp*2+1][1], bd);
                LDSM_X4(bl[jp*2][0], bl[jp*2][1], bl[jp*2+1][0], bl[jp*2+1][1], bd + 8192);
            }
            // ---- A[0], then interleave A[i+1] under MMAs of A[i] ----
            uint32_t ahf[4][4], alf[4][4];
            {
                const uint32_t ad = st + (oA[0] ^ kx);
                LDSM_X4(ahf[0][0], ahf[0][1], ahf[0][2], ahf[0][3], ad);
                LDSM_X4(alf[0][0], alf[0][1], alf[0][2], alf[0][3], ad + 8192);
            }
            #pragma unroll
            for (int i = 0; i < 4; i++) {
                if (i < 3) {
                    const uint32_t ad = st + (oA[i + 1] ^ kx);
                    LDSM_X4(ahf[i+1][0], ahf[i+1][1], ahf[i+1][2], ahf[i+1][3], ad);
                    LDSM_X4(alf[i+1][0], alf[i+1][1], alf[i+1][2], alf[i+1][3], ad + 8192);
                }
                #pragma unroll
                for (int jp = 0; jp < 2; jp++) {
                    float* c0 = acc[i][jp * 2];
                    float* c1 = acc[i][jp * 2 + 1];
                    MMA16816(c0, ahf[i][0], ahf[i][1], ahf[i][2], ahf[i][3], bh[jp*2][0], bh[jp*2][1]);
                    MMA16816(c0, ahf[i][0], ahf[i][1], ahf[i][2], ahf[i][3], bl[jp*2][0], bl[jp*2][1]);
                    MMA16816(c0, alf[i][0], alf[i][1], alf[i][2], alf[i][3], bh[jp*2][0], bh[jp*2][1]);
                    MMA16816(c1, ahf[i][0], ahf[i][1], ahf[i][2], ahf[i][3], bh[jp*2+1][0], bh[jp*2+1][1]);
                    MMA16816(c1, ahf[i][0], ahf[i][1], ahf[i][2], ahf[i][3], bl[jp*2+1][0], bl[jp*2+1][1]);
                    MMA16816(c1, alf[i][0], alf[i][1], alf[i][2], alf[i][3], bh[jp*2+1][0], bh[jp*2+1][1]);
                }
            }

            // ---- prefetch issued between kc=0 and kc=1, hidden under MMAs ----
            if (ks == 0) {
                if (kt + 2 < KT) load_stage((kt + 2) % 3, kt + 2);
                CP_COMMIT();
            }
        }
    }

    // ---- epilogue -----------------------------------------------------------
    #pragma unroll
    for (int i = 0; i < 4; i++) {
        const size_t r = m0 + wm * 64 + i * 16 + (lane >> 2);
        #pragma unroll
        for (int j = 0; j < 4; j++) {
            const size_t c = n0 + wn * 32 + j * 8 + (lane & 3) * 2;
            *reinterpret_cast<float2*>(C + r * (size_t)Ntot + c) =
                make_float2(acc[i][j][0], acc[i][j][1]);
            *reinterpret_cast<float2*>(C + (r + 8) * (size_t)Ntot + c) =
                make_float2(acc[i][j][2], acc[i][j][3]);
        }
    }
}

// ---------------------------------------------------------------------------
// Merged fp32 -> (hi, lo) bf16 split for x, w1, w2 in ONE launch.
// ---------------------------------------------------------------------------
#define GX   ((size_t)MTOK * KEL / 8)
#define GW1  ((size_t)N1 * KEL / 8)
#define GW2  ((size_t)D_MODEL * KEL / 8)
#define GTOT (GX + GW1 + GW2)

__global__ __launch_bounds__(256) void split_all(
    const float* __restrict__ x,  const float* __restrict__ w1, const float* __restrict__ w2,
    __nv_bfloat16* __restrict__ xh,  __nv_bfloat16* __restrict__ xl,
    __nv_bfloat16* __restrict__ w1h, __nv_bfloat16* __restrict__ w1l,
    __nv_bfloat16* __restrict__ w2h, __nv_bfloat16* __restrict__ w2l)
{
    size_t g = (size_t)blockIdx.x * blockDim.x + threadIdx.x;
    if (g >= GTOT) return;
    const float* src;
    __nv_bfloat16 *hi, *lo;
    size_t off;
    if (g < GX)            { src = x;  hi = xh;  lo = xl;  off = g; }
    else if (g < GX + GW1) { src = w1; hi = w1h; lo = w1l; off = g - GX; }
    else                   { src = w2; hi = w2h; lo = w2l; off = g - GX - GW1; }

    const float* s = src + off * 8;
    float4 v0 = *reinterpret_cast<const float4*>(s);
    float4 v1 = *reinterpret_cast<const float4*>(s + 4);
    float v[8] = {v0.x, v0.y, v0.z, v0.w, v1.x, v1.y, v1.z, v1.w};
    union { __nv_bfloat16 h[8]; uint4 u; } H, L;
    #pragma unroll
    for (int i = 0; i < 8; i++) {
        __nv_bfloat16 h = __float2bfloat16(v[i]);
        H.h[i] = h;
        L.h[i] = __float2bfloat16(v[i] - __bfloat162float(h));
    }
    *reinterpret_cast<uint4*>(hi + off * 8) = H.u;
    *reinterpret_cast<uint4*>(lo + off * 8) = L.u;
}

// ---------------------------------------------------------------------------
// Fused gate + causal depthwise conv(K=4) + gate; outputs split bf16 u.
// Register-rolling: each thread owns 8 d-cols x 64 consecutive tokens,
// keeps last 3 gated vectors in a 4-slot register ring -> 3 reads/element.
// Strips never cross sequence boundaries (4096 % 64 == 0).
// ---------------------------------------------------------------------------
#define STRIP 64

__global__ __launch_bounds__(256) void conv_gate_roll(
    const float* __restrict__ bcx, const float* __restrict__ cw,
    __nv_bfloat16* __restrict__ uh, __nv_bfloat16* __restrict__ ul)
{
    const int t = blockIdx.x * blockDim.x + threadIdx.x;
    if (t >= (MTOK / STRIP) * 256) return;
    const int dg    = t & 255;          // d-group (8 cols)
    const int strip = t >> 8;
    const int d0 = dg * 8;
    const size_t m0 = (size_t)strip * STRIP;
    const int s0 = (int)(m0 % SEQ);     // within-sequence start

    float w[8][4];
    #pragma unroll
    for (int j = 0; j < 8; j++) {
        float4 wv = *reinterpret_cast<const float4*>(cw + (size_t)(d0 + j) * 4);
        w[j][0] = wv.x; w[j][1] = wv.y; w[j][2] = wv.z; w[j][3] = wv.w;
    }

    // ring slots: g[(tt + q) & 3] holds gated[m0 + tt - 3 + q] for q=0..2,
    // slot (tt+3)&3 receives the current token.
    float g[4][8];
    #pragma unroll
    for (int q = 0; q < 3; q++) {
        #pragma unroll
        for (int j = 0; j < 8; j++) g[q][j] = 0.0f;
        if (s0 > 0) {   // preload gated[m0-3+q]
            const float* row = bcx + (m0 - 3 + q) * (size_t)N1;
            float4 b0 = *reinterpret_cast<const float4*>(row + d0);
            float4 b1 = *reinterpret_cast<const float4*>(row + d0 + 4);
            float4 x0 = *reinterpret_cast<const float4*>(row + 2 * D_MODEL + d0);
            float4 x1 = *reinterpret_cast<const float4*>(row + 2 * D_MODEL + d0 + 4);
            float bb[8] = {b0.x, b0.y, b0.z, b0.w, b1.x, b1.y, b1.z, b1.w};
            float xx[8] = {x0.x, x0.y, x0.z, x0.w, x1.x, x1.y, x1.z, x1.w};
            #pragma unroll
            for (int j = 0; j < 8; j++) g[q][j] = bb[j] * xx[j];
        }
    }

    #pragma unroll 4
    for (int tt = 0; tt < STRIP; tt++) {
        const size_t m = m0 + tt;
        const float* row = bcx + m * (size_t)N1;
        float4 b0 = *reinterpret_cast<const float4*>(row + d0);
        float4 b1 = *reinterpret_cast<const float4*>(row + d0 + 4);
        float4 x0 = *reinterpret_cast<const float4*>(row + 2 * D_MODEL + d0);
        float4 x1 = *reinterpret_cast<const float4*>(row + 2 * D_MODEL + d0 + 4);
        float bb[8] = {b0.x, b0.y, b0.z, b0.w, b1.x, b1.y, b1.z, b1.w};
        float xx[8] = {x0.x, x0.y, x0.z, x0.w, x1.x, x1.y, x1.z, x1.w};
        float* gc = g[(tt + 3) & 3];
        #pragma unroll
        for (int j = 0; j < 8; j++) gc[j] = bb[j] * xx[j];

        const float* g3 = g[tt & 3];        // token m-3
        const float* g2 = g[(tt + 1) & 3];  // token m-2
        const float* g1 = g[(tt + 2) & 3];  // token m-1

        float4 c0 = *reinterpret_cast<const float4*>(row + D_MODEL + d0);
        float4 c1 = *reinterpret_cast<const float4*>(row + D_MODEL + d0 + 4);
        float cc[8] = {c0.x, c0.y, c0.z, c0.w, c1.x, c1.y, c1.z, c1.w};

        union { __nv_bfloat16 h[8]; uint4 u; } H, L;
        #pragma unroll
        for (int j = 0; j < 8; j++) {
            float a = g3[j] * w[j][0];
            a = fmaf(g2[j], w[j][1], a);
            a = fmaf(g1[j], w[j][2], a);
            a = fmaf(gc[j], w[j][3], a);
            float u = cc[j] * a;
            __nv_bfloat16 h = __float2bfloat16(u);
            H.h[j] = h;
            L.h[j] = __float2bfloat16(u - __bfloat162float(h));
        }
        const size_t off = m * (size_t)D_MODEL + d0;
        *reinterpret_cast<uint4*>(uh + off) = H.u;
        *reinterpret_cast<uint4*>(ul + off) = L.u;
    }
}

// ---------------------------------------------------------------------------
extern "C" void kernel_launch(void* const* d_in, const int* in_sizes, int n_in,
                              void* d_out, int out_size)
{
    const float* x  = (const float*)d_in[0];
    const float* w1 = (const float*)d_in[1];
    const float* w2 = (const float*)d_in[2];
    const float* cw = (const float*)d_in[3];
    float* out = (float*)d_out;

    __nv_bfloat16 *xh, *xl, *w1h, *w1l, *w2h, *w2l, *uh, *ul;
    float* bcx;
    cudaGetSymbolAddress((void**)&xh,  g_xh);
    cudaGetSymbolAddress((void**)&xl,  g_xl);
    cudaGetSymbolAddress((void**)&w1h, g_w1h);
    cudaGetSymbolAddress((void**)&w1l, g_w1l);
    cudaGetSymbolAddress((void**)&w2h, g_w2h);
    cudaGetSymbolAddress((void**)&w2l, g_w2l);
    cudaGetSymbolAddress((void**)&uh,  g_uh);
    cudaGetSymbolAddress((void**)&ul,  g_ul);
    cudaGetSymbolAddress((void**)&bcx, g_bcx);

    cudaFuncSetAttribute(gemm_split,
                         cudaFuncAttributeMaxDynamicSharedMemorySize, GEMM_SMEM);

    // One merged split launch for x, w1, w2.
    split_all<<<(int)((GTOT + 255) / 256), 256>>>(
        x, w1, w2, xh, xl, w1h, w1l, w2h, w2l);

    // GEMM1: bcx = x @ w1^T
    {
        dim3 grid(N1 / 128, MTOK / 128);
        gemm_split<<<grid, 256, GEMM_SMEM>>>(xh, xl, w1h, w1l, bcx, N1);
    }

    // fused gate/conv/gate -> uh, ul (register-rolling strips)
    conv_gate_roll<<<((MTOK / STRIP) * 256) / 256, 256>>>(bcx, cw, uh, ul);

    // GEMM2: out = u @ w2^T
    {
        dim3 grid(D_MODEL / 128, MTOK / 128);
        gemm_split<<<grid, 256, GEMM_SMEM>>>(uh, ul, w2h, w2l, out, D_MODEL);
    }
}

// round 16
// speedup vs baseline: 1.0626x; 1.0003x over previous
#include <cuda_runtime.h>
#include <cuda_bf16.h>
#include <cstdint>

// ---------------------------------------------------------------------------
// GatedShortBlock via split-bf16 HMMA (mma.sync) — FINAL (session champion):
//   bcx = x @ w1^T   (16384 x 6144, K=2048)
//   u   = Cg * causal_conv4(Bg * Xg)
//   out = u @ w2^T   (16384 x 2048, K=2048)
// C = Ah*Bh^T + Ah*Bl^T + Al*Bh^T  (bf16 operands, fp32 accum, err ~2^-17)
//
// Locked-in wins (each verified by A/B bench):
//   R3  mma.sync tensor path (tcgen05 rejected at .target sm_103)   12181->5011
//   R4  warp tile 64x64 attempt -> informed final 64x32 @ 2 CTAs     5011->3929
//   R8  2 CTAs/SM (128x128 tile, 3-stage pipe, <=128 regs)           3929->3722
//   R9  B+A[0]-first LDSM, A[i+1] under MMAs of A[i]; mid-slab
//       prefetch (between ks=0 and ks=1)                             3722->3475
//   R10 register-rolling conv (3 reads/elem)                         3475->3365
//   R11 merged split kernel + hoisted XOR LDSM offsets               3365->3220
// Rejected by evidence: R5 MMA reorder, R6 16-warp CTA, R12 counter
// fusion, R13 mid-slab barrier, R14 slab-top prefetch/rolling ptrs.
// ---------------------------------------------------------------------------

#define D_MODEL 2048
#define SEQ     4096
#define MTOK    16384
#define N1      6144
#define KEL     2048
#define KT      64            // 2048 / 32 k-slabs
#define KSZ     4

// ---------------- scratch ----------------------------------------------------
__device__ __align__(16) __nv_bfloat16 g_xh [(size_t)MTOK * KEL];
__device__ __align__(16) __nv_bfloat16 g_xl [(size_t)MTOK * KEL];
__device__ __align__(16) __nv_bfloat16 g_w1h[(size_t)N1 * KEL];
__device__ __align__(16) __nv_bfloat16 g_w1l[(size_t)N1 * KEL];
__device__ __align__(16) __nv_bfloat16 g_w2h[(size_t)D_MODEL * KEL];
__device__ __align__(16) __nv_bfloat16 g_w2l[(size_t)D_MODEL * KEL];
__device__ __align__(16) __nv_bfloat16 g_uh [(size_t)MTOK * KEL];
__device__ __align__(16) __nv_bfloat16 g_ul [(size_t)MTOK * KEL];
__device__ float g_bcx[(size_t)MTOK * N1];

// ---------------- asm helpers ------------------------------------------------
__device__ __forceinline__ uint32_t smem_u32(const void* p) {
    uint32_t a;
    asm("{ .reg .u64 t; cvta.to.shared.u64 t, %1; cvt.u32.u64 %0, t; }" : "=r"(a) : "l"(p));
    return a;
}
__device__ __forceinline__ void cp16(uint32_t dst, const void* src) {
    asm volatile("cp.async.cg.shared.global [%0], [%1], 16;" :: "r"(dst), "l"(src));
}
#define CP_COMMIT() asm volatile("cp.async.commit_group;" ::: "memory")
#define CP_WAIT1()  asm volatile("cp.async.wait_group 1;" ::: "memory")

#define LDSM_X4(r0, r1, r2, r3, addr) \
    asm volatile("ldmatrix.sync.aligned.m8n8.x4.shared.b16 {%0,%1,%2,%3}, [%4];" \
        : "=r"(r0), "=r"(r1), "=r"(r2), "=r"(r3) : "r"(addr))

#define MMA16816(c, a0, a1, a2, a3, b0, b1) \
    asm volatile("mma.sync.aligned.m16n8k16.row.col.f32.bf16.bf16.f32 " \
        "{%0,%1,%2,%3}, {%4,%5,%6,%7}, {%8,%9}, {%0,%1,%2,%3};" \
        : "+f"((c)[0]), "+f"((c)[1]), "+f"((c)[2]), "+f"((c)[3]) \
        : "r"(a0), "r"(a1), "r"(a2), "r"(a3), "r"(b0), "r"(b1))

// ---------------------------------------------------------------------------
// GEMM kernel. CTA tile 128x128, 256 threads, warp grid 2(m) x 4(n),
// warp tile 64x32. Smem per stage (32KB): [Ah 8K | Al 8K | Bh 8K | Bl 8K],
// 64B rows, 16B chunks XOR-swizzled by ((row>>1)&3). 3 stages -> 2 CTAs/SM.
// ---------------------------------------------------------------------------
#define STAGE_B   32768
#define GEMM_SMEM (3 * STAGE_B)   // 98304

__global__ __launch_bounds__(256, 2) void gemm_split(
    const __nv_bfloat16* __restrict__ Ah, const __nv_bfloat16* __restrict__ Al,
    const __nv_bfloat16* __restrict__ Bh, const __nv_bfloat16* __restrict__ Bl,
    float* __restrict__ C, int Ntot)
{
    extern __shared__ __align__(1024) char smem[];
    const uint32_t sb = smem_u32(smem);
    const int tid  = threadIdx.x;
    const int lane = tid & 31;
    const int wid  = tid >> 5;
    const int wm   = wid >> 2;        // 0..1  (m)
    const int wn   = wid & 3;         // 0..3  (n)

    const size_t m0 = (size_t)blockIdx.y * 128;
    const size_t n0 = (size_t)blockIdx.x * 128;

    const char* pAh = (const char*)(Ah + m0 * (size_t)KEL);
    const char* pAl = (const char*)(Al + m0 * (size_t)KEL);
    const char* pBh = (const char*)(Bh + n0 * (size_t)KEL);
    const char* pBl = (const char*)(Bl + n0 * (size_t)KEL);

    auto load_stage = [&](int s, int kt) {
        const uint32_t st = sb + s * STAGE_B;
        const size_t kb = (size_t)kt * 64;   // byte offset along K
        #pragma unroll
        for (int rep = 0; rep < 2; rep++) {   // 128 rows x 4 chunks = 512 slots
            const int idx = rep * 256 + tid;
            const int row = idx >> 2, c = idx & 3;
            const uint32_t sw = ((((uint32_t)c) ^ ((row >> 1) & 3)) << 4);
            const uint32_t dA = st + row * 64 + sw;
            const uint32_t dB = st + 16384 + row * 64 + sw;
            const size_t so = (size_t)row * (KEL * 2) + kb + c * 16;
            cp16(dA,        pAh + so);
            cp16(dA + 8192, pAl + so);
            cp16(dB,        pBh + so);
            cp16(dB + 8192, pBl + so);
        }
    };

    // Prologue: 2 stages in flight (3rd buffer free for the first prefetch).
    load_stage(0, 0); CP_COMMIT();
    load_stage(1, 1); CP_COMMIT();

    float acc[4][4][4];
    #pragma unroll
    for (int i = 0; i < 4; i++)
        #pragma unroll
        for (int j = 0; j < 4; j++)
            #pragma unroll
            for (int q = 0; q < 4; q++) acc[i][j][q] = 0.0f;

    const int lrow8  = lane & 7;
    const int lhalfA = (lane >> 3) & 1;
    const int lkA    = lane >> 4;
    const int lhalfB = lane >> 4;
    const int lkB    = (lane >> 3) & 1;

    // kt-invariant LDSM offsets (relative to stage base). kc=1 addr = kc=0 ^ 32.
    uint32_t oA[4], oB[2];
    #pragma unroll
    for (int i = 0; i < 4; i++) {
        const int row = wm * 64 + i * 16 + lrow8 + lhalfA * 8;
        oA[i] = row * 64 + ((((uint32_t)lkA) ^ ((row >> 1) & 3)) << 4);
    }
    #pragma unroll
    for (int jp = 0; jp < 2; jp++) {
        const int nrow = wn * 32 + jp * 16 + lrow8 + lhalfB * 8;
        oB[jp] = 16384 + nrow * 64 + ((((uint32_t)lkB) ^ ((nrow >> 1) & 3)) << 4);
    }

    for (int kt = 0; kt < KT; kt++) {
        CP_WAIT1();            // stage kt complete (kt+1 may still be in flight)
        __syncthreads();

        const uint32_t st = sb + (kt % 3) * STAGE_B;
        #pragma unroll
        for (int ks = 0; ks < 2; ks++) {
            const uint32_t kx = (ks == 0) ? 0u : 32u;

            // ---- B fragments for both jp first (MMAs for i=0 need them) ----
            uint32_t bh[4][2], bl[4][2];
            #pragma unroll
            for (int jp = 0; jp < 2; jp++) {
                const uint32_t bd = st + (oB[jp] ^ kx);
                LDSM_X4(bh[jp*2][0], bh[jp*2][1], bh[jp*2+1][0], bh[jp*2+1][1], bd);
                LDSM_X4(bl[jp*2][0], bl[jp*2][1], bl[jp*2+1][0], bl[jp*2+1][1], bd + 8192);
            }
            // ---- A[0], then interleave A[i+1] under MMAs of A[i] ----
            uint32_t ahf[4][4], alf[4][4];
            {
                const uint32_t ad = st + (oA[0] ^ kx);
                LDSM_X4(ahf[0][0], ahf[0][1], ahf[0][2], ahf[0][3], ad);
                LDSM_X4(alf[0][0], alf[0][1], alf[0][2], alf[0][3], ad + 8192);
            }
            #pragma unroll
            for (int i = 0; i < 4; i++) {
                if (i < 3) {
                    const uint32_t ad = st + (oA[i + 1] ^ kx);
                    LDSM_X4(ahf[i+1][0], ahf[i+1][1], ahf[i+1][2], ahf[i+1][3], ad);
                    LDSM_X4(alf[i+1][0], alf[i+1][1], alf[i+1][2], alf[i+1][3], ad + 8192);
                }
                #pragma unroll
                for (int jp = 0; jp < 2; jp++) {
                    float* c0 = acc[i][jp * 2];
                    float* c1 = acc[i][jp * 2 + 1];
                    MMA16816(c0, ahf[i][0], ahf[i][1], ahf[i][2], ahf[i][3], bh[jp*2][0], bh[jp*2][1]);
                    MMA16816(c0, ahf[i][0], ahf[i][1], ahf[i][2], ahf[i][3], bl[jp*2][0], bl[jp*2][1]);
                    MMA16816(c0, alf[i][0], alf[i][1], alf[i][2], alf[i][3], bh[jp*2][0], bh[jp*2][1]);
                    MMA16816(c1, ahf[i][0], ahf[i][1], ahf[i][2], ahf[i][3], bh[jp*2+1][0], bh[jp*2+1][1]);
                    MMA16816(c1, ahf[i][0], ahf[i][1], ahf[i][2], ahf[i][3], bl[jp*2+1][0], bl[jp*2+1][1]);
                    MMA16816(c1, alf[i][0], alf[i][1], alf[i][2], alf[i][3], bh[jp*2+1][0], bh[jp*2+1][1]);
                }
            }

            // ---- prefetch issued between kc=0 and kc=1, hidden under MMAs ----
            if (ks == 0) {
                if (kt + 2 < KT) load_stage((kt + 2) % 3, kt + 2);
                CP_COMMIT();
            }
        }
    }

    // ---- epilogue -----------------------------------------------------------
    #pragma unroll
    for (int i = 0; i < 4; i++) {
        const size_t r = m0 + wm * 64 + i * 16 + (lane >> 2);
        #pragma unroll
        for (int j = 0; j < 4; j++) {
            const size_t c = n0 + wn * 32 + j * 8 + (lane & 3) * 2;
            *reinterpret_cast<float2*>(C + r * (size_t)Ntot + c) =
                make_float2(acc[i][j][0], acc[i][j][1]);
            *reinterpret_cast<float2*>(C + (r + 8) * (size_t)Ntot + c) =
                make_float2(acc[i][j][2], acc[i][j][3]);
        }
    }
}

// ---------------------------------------------------------------------------
// Merged fp32 -> (hi, lo) bf16 split for x, w1, w2 in ONE launch.
// ---------------------------------------------------------------------------
#define GX   ((size_t)MTOK * KEL / 8)
#define GW1  ((size_t)N1 * KEL / 8)
#define GW2  ((size_t)D_MODEL * KEL / 8)
#define GTOT (GX + GW1 + GW2)

__global__ __launch_bounds__(256) void split_all(
    const float* __restrict__ x,  const float* __restrict__ w1, const float* __restrict__ w2,
    __nv_bfloat16* __restrict__ xh,  __nv_bfloat16* __restrict__ xl,
    __nv_bfloat16* __restrict__ w1h, __nv_bfloat16* __restrict__ w1l,
    __nv_bfloat16* __restrict__ w2h, __nv_bfloat16* __restrict__ w2l)
{
    size_t g = (size_t)blockIdx.x * blockDim.x + threadIdx.x;
    if (g >= GTOT) return;
    const float* src;
    __nv_bfloat16 *hi, *lo;
    size_t off;
    if (g < GX)            { src = x;  hi = xh;  lo = xl;  off = g; }
    else if (g < GX + GW1) { src = w1; hi = w1h; lo = w1l; off = g - GX; }
    else                   { src = w2; hi = w2h; lo = w2l; off = g - GX - GW1; }

    const float* s = src + off * 8;
    float4 v0 = *reinterpret_cast<const float4*>(s);
    float4 v1 = *reinterpret_cast<const float4*>(s + 4);
    float v[8] = {v0.x, v0.y, v0.z, v0.w, v1.x, v1.y, v1.z, v1.w};
    union { __nv_bfloat16 h[8]; uint4 u; } H, L;
    #pragma unroll
    for (int i = 0; i < 8; i++) {
        __nv_bfloat16 h = __float2bfloat16(v[i]);
        H.h[i] = h;
        L.h[i] = __float2bfloat16(v[i] - __bfloat162float(h));
    }
    *reinterpret_cast<uint4*>(hi + off * 8) = H.u;
    *reinterpret_cast<uint4*>(lo + off * 8) = L.u;
}

// ---------------------------------------------------------------------------
// Fused gate + causal depthwise conv(K=4) + gate; outputs split bf16 u.
// Register-rolling: each thread owns 8 d-cols x 64 consecutive tokens,
// keeps last 3 gated vectors in a 4-slot register ring -> 3 reads/element.
// Strips never cross sequence boundaries (4096 % 64 == 0).
// ---------------------------------------------------------------------------
#define STRIP 64

__global__ __launch_bounds__(256) void conv_gate_roll(
    const float* __restrict__ bcx, const float* __restrict__ cw,
    __nv_bfloat16* __restrict__ uh, __nv_bfloat16* __restrict__ ul)
{
    const int t = blockIdx.x * blockDim.x + threadIdx.x;
    if (t >= (MTOK / STRIP) * 256) return;
    const int dg    = t & 255;          // d-group (8 cols)
    const int strip = t >> 8;
    const int d0 = dg * 8;
    const size_t m0 = (size_t)strip * STRIP;
    const int s0 = (int)(m0 % SEQ);     // within-sequence start

    float w[8][4];
    #pragma unroll
    for (int j = 0; j < 8; j++) {
        float4 wv = *reinterpret_cast<const float4*>(cw + (size_t)(d0 + j) * 4);
        w[j][0] = wv.x; w[j][1] = wv.y; w[j][2] = wv.z; w[j][3] = wv.w;
    }

    // ring slots: g[(tt + q) & 3] holds gated[m0 + tt - 3 + q] for q=0..2,
    // slot (tt+3)&3 receives the current token.
    float g[4][8];
    #pragma unroll
    for (int q = 0; q < 3; q++) {
        #pragma unroll
        for (int j = 0; j < 8; j++) g[q][j] = 0.0f;
        if (s0 > 0) {   // preload gated[m0-3+q]
            const float* row = bcx + (m0 - 3 + q) * (size_t)N1;
            float4 b0 = *reinterpret_cast<const float4*>(row + d0);
            float4 b1 = *reinterpret_cast<const float4*>(row + d0 + 4);
            float4 x0 = *reinterpret_cast<const float4*>(row + 2 * D_MODEL + d0);
            float4 x1 = *reinterpret_cast<const float4*>(row + 2 * D_MODEL + d0 + 4);
            float bb[8] = {b0.x, b0.y, b0.z, b0.w, b1.x, b1.y, b1.z, b1.w};
            float xx[8] = {x0.x, x0.y, x0.z, x0.w, x1.x, x1.y, x1.z, x1.w};
            #pragma unroll
            for (int j = 0; j < 8; j++) g[q][j] = bb[j] * xx[j];
        }
    }

    #pragma unroll 4
    for (int tt = 0; tt < STRIP; tt++) {
        const size_t m = m0 + tt;
        const float* row = bcx + m * (size_t)N1;
        float4 b0 = *reinterpret_cast<const float4*>(row + d0);
        float4 b1 = *reinterpret_cast<const float4*>(row + d0 + 4);
        float4 x0 = *reinterpret_cast<const float4*>(row + 2 * D_MODEL + d0);
        float4 x1 = *reinterpret_cast<const float4*>(row + 2 * D_MODEL + d0 + 4);
        float bb[8] = {b0.x, b0.y, b0.z, b0.w, b1.x, b1.y, b1.z, b1.w};
        float xx[8] = {x0.x, x0.y, x0.z, x0.w, x1.x, x1.y, x1.z, x1.w};
        float* gc = g[(tt + 3) & 3];
        #pragma unroll
        for (int j = 0; j < 8; j++) gc[j] = bb[j] * xx[j];

        const float* g3 = g[tt & 3];        // token m-3
        const float* g2 = g[(tt + 1) & 3];  // token m-2
        const float* g1 = g[(tt + 2) & 3];  // token m-1

        float4 c0 = *reinterpret_cast<const float4*>(row + D_MODEL + d0);
        float4 c1 = *reinterpret_cast<const float4*>(row + D_MODEL + d0 + 4);
        float cc[8] = {c0.x, c0.y, c0.z, c0.w, c1.x, c1.y, c1.z, c1.w};

        union { __nv_bfloat16 h[8]; uint4 u; } H, L;
        #pragma unroll
        for (int j = 0; j < 8; j++) {
            float a = g3[j] * w[j][0];
            a = fmaf(g2[j], w[j][1], a);
            a = fmaf(g1[j], w[j][2], a);
            a = fmaf(gc[j], w[j][3], a);
            float u = cc[j] * a;
            __nv_bfloat16 h = __float2bfloat16(u);
            H.h[j] = h;
            L.h[j] = __float2bfloat16(u - __bfloat162float(h));
        }
        const size_t off = m * (size_t)D_MODEL + d0;
        *reinterpret_cast<uint4*>(uh + off) = H.u;
        *reinterpret_cast<uint4*>(ul + off) = L.u;
    }
}

// ---------------------------------------------------------------------------
extern "C" void kernel_launch(void* const* d_in, const int* in_sizes, int n_in,
                              void* d_out, int out_size)
{
    const float* x  = (const float*)d_in[0];
    const float* w1 = (const float*)d_in[1];
    const float* w2 = (const float*)d_in[2];
    const float* cw = (const float*)d_in[3];
    float* out = (float*)d_out;

    __nv_bfloat16 *xh, *xl, *w1h, *w1l, *w2h, *w2l, *uh, *ul;
    float* bcx;
    cudaGetSymbolAddress((void**)&xh,  g_xh);
    cudaGetSymbolAddress((void**)&xl,  g_xl);
    cudaGetSymbolAddress((void**)&w1h, g_w1h);
    cudaGetSymbolAddress((void**)&w1l, g_w1l);
    cudaGetSymbolAddress((void**)&w2h, g_w2h);
    cudaGetSymbolAddress((void**)&w2l, g_w2l);
    cudaGetSymbolAddress((void**)&uh,  g_uh);
    cudaGetSymbolAddress((void**)&ul,  g_ul);
    cudaGetSymbolAddress((void**)&bcx, g_bcx);

    cudaFuncSetAttribute(gemm_split,
                         cudaFuncAttributeMaxDynamicSharedMemorySize, GEMM_SMEM);

    // One merged split launch for x, w1, w2.
    split_all<<<(int)((GTOT + 255) / 256), 256>>>(
        x, w1, w2, xh, xl, w1h, w1l, w2h, w2l);

    // GEMM1: bcx = x @ w1^T
    {
        dim3 grid(N1 / 128, MTOK / 128);
        gemm_split<<<grid, 256, GEMM_SMEM>>>(xh, xl, w1h, w1l, bcx, N1);
    }

    // fused gate/conv/gate -> uh, ul (register-rolling strips)
    conv_gate_roll<<<((MTOK / STRIP) * 256) / 256, 256>>>(bcx, cw, uh, ul);

    // GEMM2: out = u @ w2^T
    {
        dim3 grid(D_MODEL / 128, MTOK / 128);
        gemm_split<<<grid, 256, GEMM_SMEM>>>(uh, ul, w2h, w2l, out, D_MODEL);
    }
}